// round 8
// baseline (speedup 1.0000x reference)
#include <cuda_runtime.h>
#include <cuda_bf16.h>
#include <cstdint>

#define S        771                 // STATE
#define JP       832                 // padded states = 52*16
#define NB       32                  // batch
#define NT       128                 // time
#define NCTA     52                  // 52*16 = 832 output columns
#define WJ       16                  // j columns per CTA
#define NWARP    8
#define NTHR     256
#define KT       13                  // k-tiles (of 16) per k-quarter
#define INV1024  (1.0f/1024.0f)
#define LSUM     880.2969192511308f  // 127 * ln(1024)

// ---------------- persistent device state ----------------
__device__ __align__(16) __nv_bfloat16 g_Wbf[2][NB][JP];    // scaled alphas, bf16
__device__ __align__(16) float g_EME[(size_t)NT * JP * NB]; // exp(em)/1024, [t][j][b]
__device__ float    g_scp[NCTA][NB];       // per-CTA score partials
__device__ unsigned g_flags[64];           // per-CTA barrier epochs (monotone)

// flag-array grid barrier: one release store per CTA (own slot, no RMW),
// every CTA polls all 52 flags in parallel (2 acquire loads/lane + ballot).
static __device__ __forceinline__ void gsync(unsigned target, int cta) {
    __syncthreads();
    if (threadIdx.x < 32) {
        const int lane = threadIdx.x;
        if (lane == 0)
            asm volatile("st.release.gpu.global.u32 [%0],%1;"
                         :: "l"(&g_flags[cta]), "r"(target) : "memory");
        const unsigned* f0 = &g_flags[lane];
        const unsigned* f1 = &g_flags[lane + 32];
        const bool has1 = (lane + 32) < NCTA;
        bool ok;
        do {
            unsigned v0, v1 = target;
            asm volatile("ld.acquire.gpu.global.u32 %0,[%1];" : "=r"(v0) : "l"(f0) : "memory");
            if (has1)
                asm volatile("ld.acquire.gpu.global.u32 %0,[%1];" : "=r"(v1) : "l"(f1) : "memory");
            ok = ((int)(v0 - target) >= 0) && ((int)(v1 - target) >= 0);
        } while (!__all_sync(0xffffffffu, ok));
    }
    __syncthreads();
}

static __device__ __forceinline__ uint32_t pack_bf16x2(float lo, float hi) {
    uint32_t r;
    asm("cvt.rn.bf16x2.f32 %0,%1,%2;" : "=r"(r) : "f"(hi), "f"(lo));
    return r;
}
static __device__ __forceinline__ void mma16816(float* c, uint32_t a0, uint32_t a1,
                                                uint32_t a2, uint32_t a3,
                                                uint32_t b0, uint32_t b1) {
    asm volatile("mma.sync.aligned.m16n8k16.row.col.f32.bf16.bf16.f32 "
                 "{%0,%1,%2,%3},{%4,%5,%6,%7},{%8,%9},{%0,%1,%2,%3};"
                 : "+f"(c[0]), "+f"(c[1]), "+f"(c[2]), "+f"(c[3])
                 : "r"(a0), "r"(a1), "r"(a2), "r"(a3), "r"(b0), "r"(b1));
}

__global__ void __launch_bounds__(NTHR, 1)
crf_kernel(const float* __restrict__ em, const int* __restrict__ tags32,
           const float* __restrict__ mask, const float* __restrict__ trans,
           float* __restrict__ out)
{
    __shared__ __align__(16) float s_D[4][32][18];   // k-quarter partials, padded
    __shared__ float s_fin[NWARP][NB];

    const int tid  = threadIdx.x;
    const int w    = tid >> 5;
    const int lane = tid & 31;
    const int g    = lane >> 2;        // MMA group id
    const int tg   = lane & 3;         // MMA thread-in-group
    const int cta  = blockIdx.x;
    const int j0   = cta * WJ;
    const int mt   = w >> 2;           // m-tile (batch half)
    const int kq   = w & 3;            // k-quarter
    const int kb0  = kq * (KT * 16);   // k base = kq*208

    // epilogue role: thread -> (batch b_e, j-pair jp_e)
    const int b_e  = tid >> 3;
    const int jp_e = tid & 7;
    const int jl_e = jp_e * 2;

    // epoch base: my own slot (I am its only writer) — replay-safe, all equal at rest
    unsigned tgt = __ldcg(&g_flags[cta]);

    // =============== INIT ===============
    // B fragments (E^T slice) -> constant registers. B[k][n]: rows i, col j.
    uint32_t bf[KT][2][2];
    #pragma unroll
    for (int kt = 0; kt < KT; kt++) {
        #pragma unroll
        for (int nt = 0; nt < 2; nt++) {
            const int jg = j0 + nt * 8 + g;
            #pragma unroll
            for (int r = 0; r < 2; r++) {
                const int i0 = kb0 + kt * 16 + 2 * tg + 8 * r;
                float lo = (i0     < S && jg < S) ? __expf(trans[(i0    ) * S + jg]) : 0.f;
                float hi = (i0 + 1 < S && jg < S) ? __expf(trans[(i0 + 1) * S + jg]) : 0.f;
                bf[kt][nt][r] = pack_bf16x2(lo, hi);
            }
        }
    }
    // W_0 slice: W0[b][j] = exp(trans[BOS=0][j] + em[b,0,j]); padded j -> 0
    {
        const int ja = j0 + jl_e, jb = ja + 1;
        float f0 = (ja < S) ? __expf(trans[ja] + em[(size_t)b_e * NT * S + ja]) : 0.f;
        float f1 = (jb < S) ? __expf(trans[jb] + em[(size_t)b_e * NT * S + jb]) : 0.f;
        reinterpret_cast<uint32_t*>(&g_Wbf[0][b_e][j0])[jp_e] = pack_bf16x2(f0, f1);
    }
    // EME[t][j][b] = exp(em[b,t,j]) / 1024  (zero for padded j); t=0 row unused
    for (size_t id = (size_t)JP + (size_t)cta * NTHR + tid; id < (size_t)NT * JP;
         id += (size_t)NCTA * NTHR) {
        int t = (int)(id / JP), j = (int)(id % JP);
        float4* dst = reinterpret_cast<float4*>(&g_EME[id * NB]);
        if (j < S) {
            #pragma unroll
            for (int b0 = 0; b0 < NB; b0 += 4) {
                float4 v;
                v.x = __expf(em[((size_t)(b0 + 0) * NT + t) * S + j]) * INV1024;
                v.y = __expf(em[((size_t)(b0 + 1) * NT + t) * S + j]) * INV1024;
                v.z = __expf(em[((size_t)(b0 + 2) * NT + t) * S + j]) * INV1024;
                v.w = __expf(em[((size_t)(b0 + 3) * NT + t) * S + j]) * INV1024;
                dst[b0 >> 2] = v;
            }
        } else {
            float4 z = {0.f, 0.f, 0.f, 0.f};
            #pragma unroll
            for (int b0 = 0; b0 < NB; b0 += 4) dst[b0 >> 2] = z;
        }
    }
    // score gather (warp 7; lane = batch)
    if (w == NWARP - 1) {
        const bool is64 = (tags32[1] == 0);   // int64 high words zero (tags>=3)
        const int b = lane;
        float sc = 0.f;
        for (int t = cta + 1; t < NT; t += NCTA) {
            float m = mask[b * NT + t];
            int cur = is64 ? tags32[(b * NT + t) * 2]     : tags32[b * NT + t];
            int prv = is64 ? tags32[(b * NT + t - 1) * 2] : tags32[b * NT + t - 1];
            sc += (em[((size_t)b * NT + t) * S + cur] + trans[prv * S + cur]) * m;
        }
        if (cta == NCTA - 1) {
            int tag0 = is64 ? tags32[(b * NT) * 2] : tags32[b * NT];
            sc += trans[tag0] + em[(size_t)b * NT * S + tag0];
            float ms = 0.f;
            for (int t = 0; t < NT; t++) ms += mask[b * NT + t];
            int li = (int)ms - 1;
            int lt = is64 ? tags32[(b * NT + li) * 2] : tags32[b * NT + li];
            sc += trans[lt * S + 1];          // last -> EOS
        }
        g_scp[cta][lane] = sc;
    }
    ++tgt; gsync(tgt, cta);

    const int rowA = mt * 16 + g;             // A rows this thread touches
    const int kwof = (kb0 >> 1) + tg;         // u32 col index base within a W row

    // software-pipelined epilogue inputs (depend only on t, not on W)
    float mk = mask[b_e * NT + 1];
    float e0 = g_EME[((size_t)1 * JP + j0 + jl_e) * NB + b_e];
    float e1 = g_EME[((size_t)1 * JP + j0 + jl_e + 1) * NB + b_e];

    // =============== MAIN LOOP: 127 GEMM steps ===============
    for (int t = 1; t < NT; ++t) {
        const int prev = (t - 1) & 1, cur = t & 1;

        // ---- MMA: A = W[prev] streamed, B = E const regs ----
        const uint32_t* pr0 = reinterpret_cast<const uint32_t*>(g_Wbf[prev])
                            + (size_t)rowA * (JP / 2);
        const uint32_t* pr1 = pr0 + 8 * (JP / 2);
        float c0[4] = {0.f, 0.f, 0.f, 0.f};
        float c1[4] = {0.f, 0.f, 0.f, 0.f};
        #pragma unroll
        for (int kt = 0; kt < KT; kt++) {
            const int kw = kwof + kt * 8;
            uint32_t a0 = __ldcg(pr0 + kw);
            uint32_t a2 = __ldcg(pr0 + kw + 4);
            uint32_t a1 = __ldcg(pr1 + kw);
            uint32_t a3 = __ldcg(pr1 + kw + 4);
            mma16816(c0, a0, a1, a2, a3, bf[kt][0][0], bf[kt][0][1]);
            mma16816(c1, a0, a1, a2, a3, bf[kt][1][0], bf[kt][1][1]);
        }
        // partial store: D[m=b][n=j-local]
        {
            float2* p00 = reinterpret_cast<float2*>(&s_D[kq][rowA    ][0 * 8 + 2 * tg]);
            float2* p01 = reinterpret_cast<float2*>(&s_D[kq][rowA + 8][0 * 8 + 2 * tg]);
            float2* p10 = reinterpret_cast<float2*>(&s_D[kq][rowA    ][1 * 8 + 2 * tg]);
            float2* p11 = reinterpret_cast<float2*>(&s_D[kq][rowA + 8][1 * 8 + 2 * tg]);
            *p00 = make_float2(c0[0], c0[1]);
            *p01 = make_float2(c0[2], c0[3]);
            *p10 = make_float2(c1[0], c1[1]);
            *p11 = make_float2(c1[2], c1[3]);
        }
        __syncthreads();

        // ---- epilogue: reduce k-quarters, scale by exp(em)/1024, pack bf16 ----
        float s0 = 0.f, s1 = 0.f;
        #pragma unroll
        for (int q = 0; q < 4; q++) {
            s0 += s_D[q][b_e][jl_e];
            s1 += s_D[q][b_e][jl_e + 1];
        }
        float nv0 = s0 * e0, nv1 = s1 * e1;
        if (mk <= 0.f) {                       // masked step: carry old (exact 2^-10)
            uint32_t old = reinterpret_cast<const uint32_t*>(&g_Wbf[prev][b_e][j0])[jp_e];
            nv0 = __uint_as_float(old << 16)         * INV1024;
            nv1 = __uint_as_float(old & 0xFFFF0000u) * INV1024;
        }
        reinterpret_cast<uint32_t*>(&g_Wbf[cur][b_e][j0])[jp_e] = pack_bf16x2(nv0, nv1);

        // prefetch next step's epilogue inputs BEFORE the barrier
        if (t + 1 < NT) {
            mk = mask[b_e * NT + (t + 1)];
            e0 = g_EME[((size_t)(t + 1) * JP + j0 + jl_e) * NB + b_e];
            e1 = g_EME[((size_t)(t + 1) * JP + j0 + jl_e + 1) * NB + b_e];
        }

        ++tgt; gsync(tgt, cta);                // publishes W_t (release flags)
    }

    // =============== FINAL: log_z + score -> NLL (CTA 0) ===============
    if (cta == 0) {
        const int b = lane;
        float zp = 0.f;
        for (int j = w; j < S; j += NWARP)
            zp += __bfloat162float(g_Wbf[1][b][j]) * __expf(trans[j * S + 1]);
        s_fin[w][lane] = zp;
        __syncthreads();
        if (w == 0) {
            float zs = 0.f;
            #pragma unroll
            for (int ww = 0; ww < NWARP; ww++) zs += s_fin[ww][lane];
            float sc = 0.f;
            for (int c = 0; c < NCTA; c++) sc += g_scp[c][lane];
            float r = (logf(zs) + LSUM) - sc;  // log_z - score per batch
            #pragma unroll
            for (int o = 16; o; o >>= 1) r += __shfl_xor_sync(0xffffffffu, r, o);
            if (lane == 0) out[0] = r;         // NLL
        }
    }
}

extern "C" void kernel_launch(void* const* d_in, const int* in_sizes, int n_in,
                              void* d_out, int out_size)
{
    (void)in_sizes; (void)n_in; (void)out_size;
    const float* em    = (const float*)d_in[0];
    const int*   tags  = (const int*)  d_in[1];   // int64 or int32, detected in-kernel
    const float* mask  = (const float*)d_in[2];
    const float* trans = (const float*)d_in[3];
    crf_kernel<<<NCTA, NTHR>>>(em, tags, mask, trans, (float*)d_out);
}

// round 9
// speedup vs baseline: 1.7130x; 1.7130x over previous
#include <cuda_runtime.h>
#include <cuda_bf16.h>
#include <cstdint>

#define S        771                 // STATE
#define JP       832                 // padded states = 13*64
#define NB       32                  // batch
#define NT       128                 // time
#define NGR      4                   // independent batch groups
#define MB       8                   // batches per group
#define NCG      13                  // CTAs per group (13*64 = 832 j-columns)
#define NCTA     (NGR*NCG)           // 52
#define WJ       64                  // j columns per CTA
#define NWARP    8
#define NTHR     256
#define KT       13                  // k-tiles (of 16) per k-quarter
#define INV1024  (1.0f/1024.0f)
#define LSUM     880.2969192511308f  // 127 * ln(1024)

// ---------------- persistent device state ----------------
__device__ __align__(16) __nv_bfloat16 g_Wbf[2][NB][JP];    // scaled alphas, bf16
__device__ __align__(16) float g_EME[(size_t)NT * JP * NB]; // exp(em)/1024, [t][j][b]
__device__ float    g_scp[NCTA][NB];       // per-CTA score partials
__device__ unsigned g_cnt4[NGR * 32];      // per-group barrier counters (128B apart)
__device__ unsigned g_gen4[NGR * 32];      // per-group generations (monotone)

// per-group fence-light barrier: R6-proven single-thread atomic arrive + spin
static __device__ __forceinline__ void gsync(int grp, unsigned gen) {
    __syncthreads();
    if (threadIdx.x == 0) {
        unsigned prev;
        asm volatile("atom.add.release.gpu.global.u32 %0,[%1],%2;"
                     : "=r"(prev) : "l"(&g_cnt4[grp * 32]), "r"(1u) : "memory");
        if (prev == NCG - 1) {
            asm volatile("st.relaxed.gpu.global.u32 [%0],%1;"
                         :: "l"(&g_cnt4[grp * 32]), "r"(0u) : "memory");
            asm volatile("st.release.gpu.global.u32 [%0],%1;"
                         :: "l"(&g_gen4[grp * 32]), "r"(gen) : "memory");
        } else {
            unsigned v;
            do {
                asm volatile("ld.acquire.gpu.global.u32 %0,[%1];"
                             : "=r"(v) : "l"(&g_gen4[grp * 32]) : "memory");
            } while ((int)(v - gen) < 0);
        }
    }
    __syncthreads();
}

static __device__ __forceinline__ uint32_t pack_bf16x2(float lo, float hi) {
    uint32_t r;
    asm("cvt.rn.bf16x2.f32 %0,%1,%2;" : "=r"(r) : "f"(hi), "f"(lo));
    return r;
}
static __device__ __forceinline__ void mma16816(float* c, uint32_t a0, uint32_t a1,
                                                uint32_t a2, uint32_t a3,
                                                uint32_t b0, uint32_t b1) {
    asm volatile("mma.sync.aligned.m16n8k16.row.col.f32.bf16.bf16.f32 "
                 "{%0,%1,%2,%3},{%4,%5,%6,%7},{%8,%9},{%0,%1,%2,%3};"
                 : "+f"(c[0]), "+f"(c[1]), "+f"(c[2]), "+f"(c[3])
                 : "r"(a0), "r"(a1), "r"(a2), "r"(a3), "r"(b0), "r"(b1));
}

__global__ void __launch_bounds__(NTHR, 1)
crf_kernel(const float* __restrict__ em, const int* __restrict__ tags32,
           const float* __restrict__ mask, const float* __restrict__ trans,
           float* __restrict__ out)
{
    __shared__ __align__(16) float s_D[4][MB][WJ + 2];   // k-quarter partials
    __shared__ float s_fin[NWARP][NB];

    const int tid  = threadIdx.x;
    const int w    = tid >> 5;
    const int lane = tid & 31;
    const int g    = lane >> 2;        // MMA group id (row 0..7 — exactly MB rows)
    const int tg   = lane & 3;         // MMA thread-in-group
    const int cta  = blockIdx.x;
    const int grp  = cta / NCG;        // batch group
    const int cg   = cta % NCG;        // CTA within group
    const int j0   = cg * WJ;
    const int kq   = w & 3;            // k-quarter
    const int nh   = w >> 2;           // n-half (32 cols)
    const int kb0  = kq * (KT * 16);   // k base

    // epilogue role: MB rows x 32 j-pairs = 256 threads
    const int bl_e = tid >> 5;         // local batch row 0..7
    const int b_e  = grp * MB + bl_e;  // global batch
    const int jp_e = tid & 31;         // j-pair within CTA slice
    const int jl_e = jp_e * 2;

    // epoch base: own group's gen (all groups symmetric -> equal at rest)
    unsigned tgt = __ldcg(&g_gen4[grp * 32]);

    // =============== INIT ===============
    // B fragments (E^T slice) in registers: warp covers n-half (4 n-tiles)
    uint32_t bf[KT][4][2];
    #pragma unroll
    for (int kt = 0; kt < KT; kt++) {
        #pragma unroll
        for (int nt = 0; nt < 4; nt++) {
            const int jg = j0 + nh * 32 + nt * 8 + g;
            #pragma unroll
            for (int r = 0; r < 2; r++) {
                const int i0 = kb0 + kt * 16 + 2 * tg + 8 * r;
                float lo = (i0     < S && jg < S) ? __expf(trans[(i0    ) * S + jg]) : 0.f;
                float hi = (i0 + 1 < S && jg < S) ? __expf(trans[(i0 + 1) * S + jg]) : 0.f;
                bf[kt][nt][r] = pack_bf16x2(lo, hi);
            }
        }
    }
    // W_0 slice: rows = this group's 8 batches, cols = this CTA's 64 j
    {
        const int ja = j0 + jl_e, jb = ja + 1;
        float f0 = (ja < S) ? __expf(trans[ja] + em[(size_t)b_e * NT * S + ja]) : 0.f;
        float f1 = (jb < S) ? __expf(trans[jb] + em[(size_t)b_e * NT * S + jb]) : 0.f;
        reinterpret_cast<uint32_t*>(&g_Wbf[0][b_e][j0])[jp_e] = pack_bf16x2(f0, f1);
    }
    // EME[t][j][b] = exp(em[b,t,j])/1024 for OWN group's 8 batches only
    for (size_t id = (size_t)JP + (size_t)cg * NTHR + tid; id < (size_t)NT * JP;
         id += (size_t)NCG * NTHR) {
        int t = (int)(id / JP), j = (int)(id % JP);
        float4* dst = reinterpret_cast<float4*>(&g_EME[id * NB + grp * MB]);
        if (j < S) {
            #pragma unroll
            for (int q = 0; q < 2; q++) {
                const int b0 = grp * MB + q * 4;
                float4 v;
                v.x = __expf(em[((size_t)(b0 + 0) * NT + t) * S + j]) * INV1024;
                v.y = __expf(em[((size_t)(b0 + 1) * NT + t) * S + j]) * INV1024;
                v.z = __expf(em[((size_t)(b0 + 2) * NT + t) * S + j]) * INV1024;
                v.w = __expf(em[((size_t)(b0 + 3) * NT + t) * S + j]) * INV1024;
                dst[q] = v;
            }
        } else {
            float4 z = {0.f, 0.f, 0.f, 0.f};
            dst[0] = z; dst[1] = z;
        }
    }
    // score gather (warp 7; lane = batch; global CTA index as stride)
    if (w == NWARP - 1) {
        const bool is64 = (tags32[1] == 0);   // int64 high words zero (tags>=3)
        const int b = lane;
        float sc = 0.f;
        for (int t = cta + 1; t < NT; t += NCTA) {
            float m = mask[b * NT + t];
            int cur = is64 ? tags32[(b * NT + t) * 2]     : tags32[b * NT + t];
            int prv = is64 ? tags32[(b * NT + t - 1) * 2] : tags32[b * NT + t - 1];
            sc += (em[((size_t)b * NT + t) * S + cur] + trans[prv * S + cur]) * m;
        }
        if (cta == NCTA - 1) {
            int tag0 = is64 ? tags32[(b * NT) * 2] : tags32[b * NT];
            sc += trans[tag0] + em[(size_t)b * NT * S + tag0];
            float ms = 0.f;
            for (int t = 0; t < NT; t++) ms += mask[b * NT + t];
            int li = (int)ms - 1;
            int lt = is64 ? tags32[(b * NT + li) * 2] : tags32[b * NT + li];
            sc += trans[lt * S + 1];          // last -> EOS
        }
        g_scp[cta][lane] = sc;
    }
    ++tgt; gsync(grp, tgt);

    const int rowA = grp * MB + g;            // A row (m8: rows 8..15 are zero regs)
    const int kwof = (kb0 >> 1) + tg;         // u32 index base within a W row
    const uint32_t zero = 0u;

    // software-pipelined epilogue inputs (depend only on t)
    float mk = mask[b_e * NT + 1];
    float e0 = g_EME[((size_t)1 * JP + j0 + jl_e) * NB + b_e];
    float e1 = g_EME[((size_t)1 * JP + j0 + jl_e + 1) * NB + b_e];

    // =============== MAIN LOOP: 127 GEMM steps ===============
    for (int t = 1; t < NT; ++t) {
        const int prev = (t - 1) & 1, cur = t & 1;

        const uint32_t* pr0 = reinterpret_cast<const uint32_t*>(g_Wbf[prev])
                            + (size_t)rowA * (JP / 2);
        float c[4][4];
        #pragma unroll
        for (int nt = 0; nt < 4; nt++) { c[nt][0]=0.f; c[nt][1]=0.f; c[nt][2]=0.f; c[nt][3]=0.f; }
        #pragma unroll
        for (int kt = 0; kt < KT; kt++) {
            const int kw = kwof + kt * 8;
            uint32_t a0 = __ldcg(pr0 + kw);
            uint32_t a2 = __ldcg(pr0 + kw + 4);
            #pragma unroll
            for (int nt = 0; nt < 4; nt++)
                mma16816(c[nt], a0, zero, a2, zero, bf[kt][nt][0], bf[kt][nt][1]);
        }
        // partial store (rows 0..7 only; rows 8..15 of the m16 tile are waste)
        #pragma unroll
        for (int nt = 0; nt < 4; nt++) {
            float2* p = reinterpret_cast<float2*>(&s_D[kq][g][nh * 32 + nt * 8 + 2 * tg]);
            *p = make_float2(c[nt][0], c[nt][1]);
        }
        __syncthreads();

        // ---- epilogue: reduce k-quarters, scale by exp(em)/1024, pack bf16 ----
        float s0 = 0.f, s1 = 0.f;
        #pragma unroll
        for (int q = 0; q < 4; q++) {
            s0 += s_D[q][bl_e][jl_e];
            s1 += s_D[q][bl_e][jl_e + 1];
        }
        float nv0 = s0 * e0, nv1 = s1 * e1;
        if (mk <= 0.f) {                       // masked step: carry old (exact 2^-10)
            uint32_t old = reinterpret_cast<const uint32_t*>(&g_Wbf[prev][b_e][j0])[jp_e];
            nv0 = __uint_as_float(old << 16)         * INV1024;
            nv1 = __uint_as_float(old & 0xFFFF0000u) * INV1024;
        }
        reinterpret_cast<uint32_t*>(&g_Wbf[cur][b_e][j0])[jp_e] = pack_bf16x2(nv0, nv1);

        // prefetch next step's epilogue inputs BEFORE the barrier
        if (t + 1 < NT) {
            mk = mask[b_e * NT + (t + 1)];
            e0 = g_EME[((size_t)(t + 1) * JP + j0 + jl_e) * NB + b_e];
            e1 = g_EME[((size_t)(t + 1) * JP + j0 + jl_e + 1) * NB + b_e];
        }

        ++tgt; gsync(grp, tgt);                // publishes W_t within the group
    }

    // =============== FINAL: log_z + score -> NLL (CTA 0) ===============
    if (cta == 0) {
        // wait for the other 3 groups to finish their last step (same epoch count)
        if (tid < NGR - 1) {
            const unsigned* gp = &g_gen4[(tid + 1) * 32];
            unsigned v;
            do {
                asm volatile("ld.acquire.gpu.global.u32 %0,[%1];" : "=r"(v) : "l"(gp) : "memory");
            } while ((int)(v - tgt) < 0);
        }
        __syncthreads();

        const int b = lane;
        float zp = 0.f;
        for (int j = w; j < S; j += NWARP)
            zp += __bfloat162float(g_Wbf[1][b][j]) * __expf(trans[j * S + 1]);
        s_fin[w][lane] = zp;
        __syncthreads();
        if (w == 0) {
            float zs = 0.f;
            #pragma unroll
            for (int ww = 0; ww < NWARP; ww++) zs += s_fin[ww][lane];
            float sc = 0.f;
            for (int c2 = 0; c2 < NCTA; c2++) sc += g_scp[c2][lane];
            float r = (logf(zs) + LSUM) - sc;  // log_z - score per batch
            #pragma unroll
            for (int o = 16; o; o >>= 1) r += __shfl_xor_sync(0xffffffffu, r, o);
            if (lane == 0) out[0] = r;         // NLL
        }
    }
}

extern "C" void kernel_launch(void* const* d_in, const int* in_sizes, int n_in,
                              void* d_out, int out_size)
{
    (void)in_sizes; (void)n_in; (void)out_size;
    const float* em    = (const float*)d_in[0];
    const int*   tags  = (const int*)  d_in[1];   // int64 or int32, detected in-kernel
    const float* mask  = (const float*)d_in[2];
    const float* trans = (const float*)d_in[3];
    crf_kernel<<<NCTA, NTHR>>>(em, tags, mask, trans, (float*)d_out);
}

// round 10
// speedup vs baseline: 3.0893x; 1.8035x over previous
#include <cuda_runtime.h>
#include <cuda_bf16.h>
#include <cstdint>

#define S        771                 // STATE
#define JP       832                 // padded states = 13*64
#define NB       32                  // batch
#define NT       128                 // time
#define NGR      4                   // independent batch groups (= clusters)
#define MB       8                   // batches per group
#define NCG      13                  // CTAs per cluster (13*64 = 832 j-columns)
#define NCTA     (NGR*NCG)           // 52
#define WJ       64                  // j columns per CTA
#define NWARP    8
#define NTHR     256
#define KT       13                  // k-tiles (of 16) per k-quarter
#define ROWU     420                 // padded u32 row stride (mod 32 = 4: no LDS conflicts)
#define INV1024  (1.0f/1024.0f)
#define LSUM     880.2969192511308f  // 127 * ln(1024)

// ---------------- persistent device state ----------------
__device__ __align__(16) float g_EME[(size_t)NT * JP * NB]; // exp(em)/1024, [t][j][b]
__device__ unsigned g_scp[NCTA][NB];       // per-CTA score partials (f32 bits)
__device__ unsigned g_zfin[NB];            // per-batch final z-sums (f32 bits)
__device__ unsigned g_fin[NGR * 32];       // per-group done epochs (monotone)

static __device__ __forceinline__ uint32_t smem_u32(const void* p) {
    uint32_t a;
    asm("{ .reg .u64 t; cvta.to.shared.u64 t, %1; cvt.u32.u64 %0, t; }" : "=r"(a) : "l"(p));
    return a;
}
static __device__ __forceinline__ uint32_t pack_bf16x2(float lo, float hi) {
    uint32_t r;
    asm("cvt.rn.bf16x2.f32 %0,%1,%2;" : "=r"(r) : "f"(hi), "f"(lo));
    return r;
}
static __device__ __forceinline__ void mma16816(float* c, uint32_t a0, uint32_t a1,
                                                uint32_t a2, uint32_t a3,
                                                uint32_t b0, uint32_t b1) {
    asm volatile("mma.sync.aligned.m16n8k16.row.col.f32.bf16.bf16.f32 "
                 "{%0,%1,%2,%3},{%4,%5,%6,%7},{%8,%9},{%0,%1,%2,%3};"
                 : "+f"(c[0]), "+f"(c[1]), "+f"(c[2]), "+f"(c[3])
                 : "r"(a0), "r"(a1), "r"(a2), "r"(a3), "r"(b0), "r"(b1));
}
#define CLUSTER_ARRIVE() asm volatile("barrier.cluster.arrive.aligned;" ::: "memory")
#define CLUSTER_WAIT()   asm volatile("barrier.cluster.wait.aligned;"   ::: "memory")
static __device__ __forceinline__ void st_rel(unsigned* p, unsigned v) {
    asm volatile("st.release.gpu.global.b32 [%0],%1;" :: "l"(p), "r"(v) : "memory");
}
static __device__ __forceinline__ unsigned ld_acq(const unsigned* p) {
    unsigned v;
    asm volatile("ld.acquire.gpu.global.b32 %0,[%1];" : "=r"(v) : "l"(p) : "memory");
    return v;
}

__global__ void __launch_bounds__(NTHR, 1)
crf_kernel(const float* __restrict__ em, const int* __restrict__ tags32,
           const float* __restrict__ mask, const float* __restrict__ trans,
           float* __restrict__ out)
{
    __shared__ uint32_t sW[2][MB][ROWU];             // full group W, bf16x2, dbl-buf
    __shared__ __align__(16) float s_D[4][MB][WJ + 2];

    const int tid  = threadIdx.x;
    const int w    = tid >> 5;
    const int lane = tid & 31;
    const int g    = lane >> 2;        // MMA row within group (0..7 = MB)
    const int tg   = lane & 3;
    const int cta  = blockIdx.x;
    const int grp  = cta / NCG;
    const int cg   = cta % NCG;        // == cluster ctarank (1-D cluster)
    const int j0   = cg * WJ;
    const int kq   = w & 3;            // k-quarter
    const int nh   = w >> 2;           // n-half
    const int kb0  = kq * (KT * 16);

    // epilogue role: MB rows x 32 j-pairs
    const int bl_e = tid >> 5;
    const int b_e  = grp * MB + bl_e;
    const int jp_e = tid & 31;
    const int jl_e = jp_e * 2;

    unsigned finbase = 0;
    if (cg == 0 && tid == 0) finbase = __ldcg(&g_fin[grp * 32]);

    // DSMEM remote bases for sW (one per cluster rank)
    const uint32_t sWb = smem_u32(&sW[0][0][0]);
    uint32_t rbase[NCG];
    #pragma unroll
    for (int r = 0; r < NCG; r++)
        asm("mapa.shared::cluster.u32 %0, %1, %2;" : "=r"(rbase[r]) : "r"(sWb), "r"(r));
    const uint32_t myoff = (uint32_t)(bl_e * ROWU + (j0 >> 1) + jp_e) * 4u;

    // =============== INIT ===============
    // B fragments (E^T slice) in registers
    uint32_t bfr[KT][4][2];
    #pragma unroll
    for (int kt = 0; kt < KT; kt++) {
        #pragma unroll
        for (int nt = 0; nt < 4; nt++) {
            const int jg = j0 + nh * 32 + nt * 8 + g;
            #pragma unroll
            for (int r = 0; r < 2; r++) {
                const int i0 = kb0 + kt * 16 + 2 * tg + 8 * r;
                float lo = (i0     < S && jg < S) ? __expf(trans[(i0    ) * S + jg]) : 0.f;
                float hi = (i0 + 1 < S && jg < S) ? __expf(trans[(i0 + 1) * S + jg]) : 0.f;
                bfr[kt][nt][r] = pack_bf16x2(lo, hi);
            }
        }
    }
    // full W_0 for this group's 8 batches (every CTA computes its own copy)
    for (int idx = tid; idx < MB * (JP / 2); idx += NTHR) {
        int r = idx / (JP / 2), cu = idx % (JP / 2);
        int b = grp * MB + r, ja = 2 * cu, jb = ja + 1;
        float f0 = (ja < S) ? __expf(trans[ja] + em[(size_t)b * NT * S + ja]) : 0.f;
        float f1 = (jb < S) ? __expf(trans[jb] + em[(size_t)b * NT * S + jb]) : 0.f;
        sW[0][r][cu] = pack_bf16x2(f0, f1);
    }
    // EME[t][j][b] = exp(em[b,t,j])/1024 for OWN group's batches (striped by cg)
    for (size_t id = (size_t)JP + (size_t)cg * NTHR + tid; id < (size_t)NT * JP;
         id += (size_t)NCG * NTHR) {
        int t = (int)(id / JP), j = (int)(id % JP);
        float4* dst = reinterpret_cast<float4*>(&g_EME[id * NB + grp * MB]);
        if (j < S) {
            #pragma unroll
            for (int q = 0; q < 2; q++) {
                const int b0 = grp * MB + q * 4;
                float4 v;
                v.x = __expf(em[((size_t)(b0 + 0) * NT + t) * S + j]) * INV1024;
                v.y = __expf(em[((size_t)(b0 + 1) * NT + t) * S + j]) * INV1024;
                v.z = __expf(em[((size_t)(b0 + 2) * NT + t) * S + j]) * INV1024;
                v.w = __expf(em[((size_t)(b0 + 3) * NT + t) * S + j]) * INV1024;
                dst[q] = v;
            }
        } else {
            float4 z = {0.f, 0.f, 0.f, 0.f};
            dst[0] = z; dst[1] = z;
        }
    }
    // score gather (warp 7; lane = batch)
    if (w == NWARP - 1) {
        const bool is64 = (tags32[1] == 0);   // int64 high words zero (tags>=3)
        const int b = lane;
        float sc = 0.f;
        for (int t = cta + 1; t < NT; t += NCTA) {
            float m = mask[b * NT + t];
            int cur = is64 ? tags32[(b * NT + t) * 2]     : tags32[b * NT + t];
            int prv = is64 ? tags32[(b * NT + t - 1) * 2] : tags32[b * NT + t - 1];
            sc += (em[((size_t)b * NT + t) * S + cur] + trans[prv * S + cur]) * m;
        }
        if (cta == NCTA - 1) {
            int tag0 = is64 ? tags32[(b * NT) * 2] : tags32[b * NT];
            sc += trans[tag0] + em[(size_t)b * NT * S + tag0];
            float ms = 0.f;
            for (int t = 0; t < NT; t++) ms += mask[b * NT + t];
            int li = (int)ms - 1;
            int lt = is64 ? tags32[(b * NT + li) * 2] : tags32[b * NT + li];
            sc += trans[lt * S + 1];          // last -> EOS
        }
        st_rel(&g_scp[cta][lane], __float_as_uint(sc));
    }
    __syncthreads();
    CLUSTER_ARRIVE(); CLUSTER_WAIT();          // EME + own sW[0] ready cluster-wide

    const int kwof = (kb0 >> 1) + tg;
    const uint32_t zero = 0u;

    // software-pipelined epilogue inputs
    float mk = mask[b_e * NT + 1];
    float e0 = g_EME[((size_t)1 * JP + j0 + jl_e) * NB + b_e];
    float e1 = g_EME[((size_t)1 * JP + j0 + jl_e + 1) * NB + b_e];

    // =============== MAIN LOOP: 127 GEMM steps ===============
    for (int t = 1; t < NT; ++t) {
        const int prev = (t - 1) & 1, cur = t & 1;
        const uint32_t* aRow = &sW[prev][g][0];

        float c[4][4];
        #pragma unroll
        for (int nt = 0; nt < 4; nt++) { c[nt][0]=0.f; c[nt][1]=0.f; c[nt][2]=0.f; c[nt][3]=0.f; }
        #pragma unroll
        for (int kt = 0; kt < KT; kt++) {
            const int kw = kwof + kt * 8;
            uint32_t a0 = aRow[kw];            // local LDS, conflict-free (ROWU%32==4)
            uint32_t a2 = aRow[kw + 4];
            #pragma unroll
            for (int nt = 0; nt < 4; nt++)
                mma16816(c[nt], a0, zero, a2, zero, bfr[kt][nt][0], bfr[kt][nt][1]);
        }
        #pragma unroll
        for (int nt = 0; nt < 4; nt++) {
            float2* p = reinterpret_cast<float2*>(&s_D[kq][g][nh * 32 + nt * 8 + 2 * tg]);
            *p = make_float2(c[nt][0], c[nt][1]);
        }
        __syncthreads();

        // ---- epilogue: reduce k-quarters, scale, pack, broadcast to cluster ----
        float s0 = 0.f, s1 = 0.f;
        #pragma unroll
        for (int q = 0; q < 4; q++) {
            s0 += s_D[q][bl_e][jl_e];
            s1 += s_D[q][bl_e][jl_e + 1];
        }
        float nv0 = s0 * e0, nv1 = s1 * e1;
        if (mk <= 0.f) {                       // masked step: carry old (exact 2^-10)
            uint32_t old = sW[prev][bl_e][(j0 >> 1) + jp_e];
            nv0 = __uint_as_float(old << 16)         * INV1024;
            nv1 = __uint_as_float(old & 0xFFFF0000u) * INV1024;
        }
        const uint32_t outv = pack_bf16x2(nv0, nv1);
        const uint32_t off  = myoff + (uint32_t)cur * (MB * ROWU * 4);
        #pragma unroll
        for (int r = 0; r < NCG; r++)
            asm volatile("st.shared::cluster.u32 [%0], %1;"
                         :: "r"(rbase[r] + off), "r"(outv) : "memory");
        __syncthreads();                        // all CTA stores issued before arrive
        CLUSTER_ARRIVE();                       // release: DSMEM stores ordered

        if (t + 1 < NT) {                       // prefetch between arrive and wait
            mk = mask[b_e * NT + (t + 1)];
            e0 = g_EME[((size_t)(t + 1) * JP + j0 + jl_e) * NB + b_e];
            e1 = g_EME[((size_t)(t + 1) * JP + j0 + jl_e + 1) * NB + b_e];
        }
        CLUSTER_WAIT();                         // acquire: W_t visible
    }

    // =============== FINAL: per-group z, then CTA 0 reduces ===============
    if (cg == 0) {                              // group leader: zp for its 8 batches
        float zp = 0.f;                         // warp w -> local row w
        for (int cu = lane; cu < JP / 2; cu += 32) {
            uint32_t u = sW[1][w][cu];          // (NT-1)&1 == 1
            int ja = 2 * cu, jb = ja + 1;
            if (ja < S) zp += __uint_as_float(u << 16)         * __expf(trans[ja * S + 1]);
            if (jb < S) zp += __uint_as_float(u & 0xFFFF0000u) * __expf(trans[jb * S + 1]);
        }
        #pragma unroll
        for (int o = 16; o; o >>= 1) zp += __shfl_xor_sync(0xffffffffu, zp, o);
        if (lane == 0) st_rel(&g_zfin[grp * MB + w], __float_as_uint(zp));
        __syncthreads();
        if (tid == 0) st_rel(&g_fin[grp * 32], finbase + 1u);
    }

    if (cta == 0) {
        if (tid == 0) {                         // wait for the other 3 groups
            for (int gg = 1; gg < NGR; gg++)
                while ((int)(ld_acq(&g_fin[gg * 32]) - (finbase + 1u)) < 0) { }
        }
        __syncthreads();
        if (w == 0) {
            const int b = lane;
            float zs = __uint_as_float(ld_acq(&g_zfin[b]));
            float sc = 0.f;
            for (int c2 = 0; c2 < NCTA; c2++)
                sc += __uint_as_float(ld_acq(&g_scp[c2][b]));
            float r = (logf(zs) + LSUM) - sc;   // log_z - score per batch
            #pragma unroll
            for (int o = 16; o; o >>= 1) r += __shfl_xor_sync(0xffffffffu, r, o);
            if (lane == 0) out[0] = r;          // NLL
        }
    }
}

extern "C" void kernel_launch(void* const* d_in, const int* in_sizes, int n_in,
                              void* d_out, int out_size)
{
    (void)in_sizes; (void)n_in; (void)out_size;
    const float* em    = (const float*)d_in[0];
    const int*   tags  = (const int*)  d_in[1];   // int64 or int32, detected in-kernel
    const float* mask  = (const float*)d_in[2];
    const float* trans = (const float*)d_in[3];
    float* o = (float*)d_out;

    cudaFuncSetAttribute(crf_kernel, cudaFuncAttributeNonPortableClusterSizeAllowed, 1);

    cudaLaunchConfig_t cfg = {};
    cfg.gridDim  = {NCTA, 1, 1};
    cfg.blockDim = {NTHR, 1, 1};
    cfg.dynamicSmemBytes = 0;
    cfg.stream = 0;
    cudaLaunchAttribute at[1];
    at[0].id = cudaLaunchAttributeClusterDimension;
    at[0].val.clusterDim = {NCG, 1, 1};
    cfg.attrs = at;
    cfg.numAttrs = 1;
    cudaLaunchKernelEx(&cfg, crf_kernel, em, tags, mask, trans, o);
}